// round 4
// baseline (speedup 1.0000x reference)
#include <cuda_runtime.h>
#include <math.h>

#define BB 32
#define CC 3
#define HH 512
#define WW 512
#define HW (HH * WW)
#define PI_F 3.14159f

// Scratch: per-batch inverse homographies, light params, batch-invariant
// moire field (3 MB, L2-resident, reused 32x).
__device__ float g_minv[BB][9];
__device__ float g_light[3];   // xf, yf, 1/max_len
__device__ float g_moire[CC * HW];

// ---------------------------------------------------------------------------
// Prep: moire field (bulk) + block-0 side jobs: closed-form (Heckbert)
// homography per batch in fp32 and the light-spot params. The homography is
// unique up to scale and only used through a perspective divide, so the
// adjugate (un-normalized inverse) is sufficient.
// ---------------------------------------------------------------------------
__global__ void prep_kernel(const float* __restrict__ theta,
                            const float* __restrict__ center,
                            const float* __restrict__ dst_offsets,
                            const int* __restrict__ light_xy) {
    if (blockIdx.x == 0) {
        int b = threadIdx.x;
        if (b == 32) {
            float xf = (float)light_xy[0];
            float yf = (float)light_xy[1];
            const float S = 512.0f;
            float d0 = sqrtf(xf * xf + yf * yf);
            float d1 = sqrtf((xf - S) * (xf - S) + yf * yf);
            float d2 = sqrtf(xf * xf + (yf - S) * (yf - S));
            float d3 = sqrtf((xf - S) * (xf - S) + (yf - S) * (yf - S));
            float ml = fmaxf(fmaxf(d0, d1), fmaxf(d2, d3)) * 0.5f;
            g_light[0] = xf;
            g_light[1] = yf;
            g_light[2] = 1.0f / ml;
        }
        if (b < BB) {
            const float S = 512.0f;
            // src corners: k=0:(0,0) k=1:(0,S) k=2:(S,0) k=3:(S,S)
            const float sxc[4] = {0.0f, 0.0f, 512.0f, 512.0f};
            const float syc[4] = {0.0f, 512.0f, 0.0f, 512.0f};
            float du[4], dv[4];
            for (int k = 0; k < 4; k++) {
                du[k] = sxc[k] + dst_offsets[(b * 4 + k) * 2 + 0];
                dv[k] = syc[k] + dst_offsets[(b * 4 + k) * 2 + 1];
            }
            // Unit-square param (s,t)=(x/S, y/S):
            // (0,0)->dst0 (1,0)->dst2 (1,1)->dst3 (0,1)->dst1
            float u0 = du[0], u1 = du[2], u2 = du[3], u3 = du[1];
            float v0 = dv[0], v1 = dv[2], v2 = dv[3], v3 = dv[1];
            float sx = u0 - u1 + u2 - u3;
            float sy = v0 - v1 + v2 - v3;
            float dx1 = u1 - u2, dx2 = u3 - u2;
            float dy1 = v1 - v2, dy2 = v3 - v2;
            float den = dx1 * dy2 - dy1 * dx2;
            float g = (sx * dy2 - sy * dx2) / den;
            float h = (dx1 * sy - dy1 * sx) / den;
            float a = u1 - u0 + g * u1;
            float bq = u3 - u0 + h * u3;
            float c = u0;
            float d = v1 - v0 + g * v1;
            float e = v3 - v0 + h * v3;
            float f = v0;
            // Map in (x,y): u = (a x + b y + cS)/(g x + h y + S)
            float m0 = a,  m1 = bq, m2 = c * S;
            float m3 = d,  m4 = e,  m5 = f * S;
            float m6 = g,  m7 = h,  m8 = S;
            float inv9[9] = {
                m4 * m8 - m5 * m7, m2 * m7 - m1 * m8, m1 * m5 - m2 * m4,
                m5 * m6 - m3 * m8, m0 * m8 - m2 * m6, m2 * m3 - m0 * m5,
                m3 * m7 - m4 * m6, m1 * m6 - m0 * m7, m0 * m4 - m1 * m3};
            float nrm = 1.0f / inv9[8];
            for (int k = 0; k < 9; k++) g_minv[b][k] = inv9[k] * nrm;
        }
    }

    int idx = blockIdx.x * blockDim.x + threadIdx.x;
    if (idx >= CC * HW) return;
    int c = idx / HW;
    int rem = idx - c * HW;
    int i = rem >> 9;
    int j = rem & (WW - 1);

    float dx = (float)i - center[c * 2 + 0];
    float dy = (float)j - center[c * 2 + 1];
    float z1 = 0.5f + 0.5f * cosf(2.0f * PI_F * sqrtf(dx * dx + dy * dy));
    float th = theta[c] / 180.0f * PI_F;
    float z2 = 0.5f + 0.5f * cosf(cosf(th) * (float)j + sinf(th) * (float)i);
    g_moire[idx] = fminf(z1, z2) * 2.0f - 1.0f;
}

// ---------------------------------------------------------------------------
// Fused main kernel, 4 pixels per thread (one row segment), float4 streaming
// I/O for cover/noise/moire/outputs; scalar gathers for the warp taps only.
// ---------------------------------------------------------------------------
__global__ void main_kernel(const float* __restrict__ imgs,
                            const float* __restrict__ noise,
                            const float* __restrict__ cover,
                            const float* __restrict__ hue_shift,
                            const float* __restrict__ bright,
                            const float* __restrict__ contrast,
                            float* __restrict__ out) {
    int t = blockIdx.x * blockDim.x + threadIdx.x;
    int p4 = t * 4;                 // first pixel of the quad
    if (p4 >= HW) return;
    int b = blockIdx.y;
    int i = p4 >> 9;                // row (same for all 4 pixels)
    int j0 = p4 & (WW - 1);         // first col

    const size_t n_img = (size_t)BB * CC * HW;
    size_t base = (size_t)b * CC * HW + p4;

    // Streaming loads first: independent of the gather chain (max MLP).
    float4 cv[3], nz[3], mo[3];
#pragma unroll
    for (int c = 0; c < 3; c++) {
        cv[c] = *reinterpret_cast<const float4*>(cover + base + (size_t)c * HW);
        nz[c] = *reinterpret_cast<const float4*>(noise + base + (size_t)c * HW);
        mo[c] = *reinterpret_cast<const float4*>(g_moire + c * HW + p4);
    }

    // Row-constant parts of the projective map.
    const float* mv = g_minv[b];
    float y = (float)i;
    float cA = mv[1] * y + mv[2];
    float cB = mv[4] * y + mv[5];
    float cW = mv[7] * y + mv[8];

    int cx0[4], cx1[4], cy0[4], cy1[4];
    float wx[4], wy[4];
    bool vx0[4], vx1[4], vy0[4], vy1[4];
#pragma unroll
    for (int q = 0; q < 4; q++) {
        float x = (float)(j0 + q);
        float wq = mv[6] * x + cW;
        float invw = __fdividef(1.0f, wq);
        float sxv = (mv[0] * x + cA) * invw;
        float syv = (mv[3] * x + cB) * invw;
        float x0f = floorf(sxv), y0f = floorf(syv);
        wx[q] = sxv - x0f;
        wy[q] = syv - y0f;
        int x0 = (int)x0f, y0 = (int)y0f;
        int x1 = x0 + 1, y1 = y0 + 1;
        vx0[q] = (x0 >= 0) && (x0 < WW);
        vx1[q] = (x1 >= 0) && (x1 < WW);
        vy0[q] = (y0 >= 0) && (y0 < HH);
        vy1[q] = (y1 >= 0) && (y1 < HH);
        cx0[q] = min(max(x0, 0), WW - 1);
        cx1[q] = min(max(x1, 0), WW - 1);
        cy0[q] = min(max(y0, 0), HH - 1) * WW;
        cy1[q] = min(max(y1, 0), HH - 1) * WW;
    }

    float ct = contrast[b];
    float br = bright[b];

    const float* imb = imgs + (size_t)b * CC * HW;
    float v[3][4];
#pragma unroll
    for (int c = 0; c < 3; c++) {
        const float* im = imb + c * HW;
#pragma unroll
        for (int q = 0; q < 4; q++) {
            float v00 = (vy0[q] && vx0[q]) ? im[cy0[q] + cx0[q]] : 0.0f;
            float v01 = (vy0[q] && vx1[q]) ? im[cy0[q] + cx1[q]] : 0.0f;
            float v10 = (vy1[q] && vx0[q]) ? im[cy1[q] + cx0[q]] : 0.0f;
            float v11 = (vy1[q] && vx1[q]) ? im[cy1[q] + cx1[q]] : 0.0f;
            float val = (1.0f - wy[q]) * ((1.0f - wx[q]) * v00 + wx[q] * v01) +
                        wy[q] * ((1.0f - wx[q]) * v10 + wx[q] * v11);
            float o = val * ct + hue_shift[b * 3 + c] + br;
            v[c][q] = fminf(fmaxf(o, -1.0f), 1.0f);
        }
    }

    // light spot (row-constant di)
    float xf = g_light[0], yf = g_light[1], rml = g_light[2];
    float di = (float)i - xf;
    float di2 = di * di;

    float lum[4], light[4];
#pragma unroll
    for (int q = 0; q < 4; q++) {
        lum[q] = (0.3f * v[0][q] + 0.6f * v[1][q] + 0.1f * v[2][q]) *
                 (1.0f / 3.0f);
        float dj = (float)(j0 + q) - yf;
        float dl = sqrtf(di2 + dj * dj);
        float lw = 1.0f - dl * rml;
        light[q] = (lw > 0.0f) ? lw : 0.0f;
    }

    const float kn = 0.031622776601683794f;  // sqrt(0.001)
#pragma unroll
    for (int c = 0; c < 3; c++) {
        float4 o4;
        float* op = &o4.x;
        const float* nzp = &nz[c].x;
        const float* mop = &mo[c].x;
#pragma unroll
        for (int q = 0; q < 4; q++) {
            float o = 0.7f * v[c][q] + 0.3f * lum[q];
            o = o + light[q];
            o = o + mop[q] * 0.2f;
            o = o + kn * nzp[q];
            op[q] = o;
        }
        size_t off = base + (size_t)c * HW;
        *reinterpret_cast<float4*>(out + off) = o4;
        *reinterpret_cast<float4*>(out + n_img + off) = cv[c];
    }
}

// ---------------------------------------------------------------------------
// Inputs (metadata order): 0 imgs, 1 cover, 2 dst_offsets, 3 hue_shift,
// 4 bright, 5 contrast, 6 light_xy(int32), 7 moire_theta, 8 moire_center,
// 9 noise. Output: [noised | cover], 2 * 32*3*512*512 floats.
// ---------------------------------------------------------------------------
extern "C" void kernel_launch(void* const* d_in, const int* in_sizes, int n_in,
                              void* d_out, int out_size) {
    const float* imgs        = (const float*)d_in[0];
    const float* cover       = (const float*)d_in[1];
    const float* dst_offsets = (const float*)d_in[2];
    const float* hue_shift   = (const float*)d_in[3];
    const float* bright      = (const float*)d_in[4];
    const float* contrast    = (const float*)d_in[5];
    const int*   light_xy    = (const int*)d_in[6];
    const float* moire_theta = (const float*)d_in[7];
    const float* moire_cent  = (const float*)d_in[8];
    const float* noise       = (const float*)d_in[9];
    float* out = (float*)d_out;

    prep_kernel<<<(CC * HW + 255) / 256, 256>>>(moire_theta, moire_cent,
                                                dst_offsets, light_xy);

    dim3 grid(HW / (256 * 4), BB);
    main_kernel<<<grid, 256>>>(imgs, noise, cover, hue_shift, bright, contrast,
                               out);
}